// round 2
// baseline (speedup 1.0000x reference)
#include <cuda_runtime.h>

#define NTOK 8192
#define DIM  2048
#define NE   8
#define NPAT 64          // pattern id = a*8+b (a<b), sparse over 64 slots
#define TM   64
#define TN   64
#define TK   16
#define MAX_ITEMS 256    // worst case sum(ceil(cnt/TM)) <= 8192/64 + 64 = 192

// ---- scratch (allocation-free: __device__ globals) ----
__device__ float g_Wsum[(size_t)DIM * DIM];   // 16 MB
__device__ float g_bsum[DIM];
__device__ int   g_cnt[NPAT];
__device__ int   g_list[NPAT * NTOK];         // 2 MB: token lists per pattern
__device__ int   g_items[MAX_ITEMS * 2];      // (pid, tile) work items
__device__ int   g_total;

// ============================================================
// Kernel 1: Wsum = sum_e We[e], bsum = sum_e be[e], zero counters
// ============================================================
__global__ __launch_bounds__(256) void prep_kernel(const float* __restrict__ We,
                                                   const float* __restrict__ be) {
    size_t idx = (size_t)blockIdx.x * blockDim.x + threadIdx.x;
    if (idx < (size_t)DIM * DIM) {
        float s = 0.f;
#pragma unroll
        for (int e = 0; e < NE; e++) s += We[(size_t)e * DIM * DIM + idx];
        g_Wsum[idx] = s;
    }
    if (idx < DIM) {
        float s = 0.f;
#pragma unroll
        for (int e = 0; e < NE; e++) s += be[e * DIM + idx];
        g_bsum[idx] = s;
    }
    if (idx < NPAT) g_cnt[idx] = 0;
    if (idx == 0) g_total = 0;
}

// ============================================================
// Kernel 2: gate scores (fp64 accumulation for ranking fidelity),
// find the 2 excluded experts (smallest scores; tie -> larger index
// excluded, matching jax top_k's lower-index-wins), bucket token.
// ============================================================
__global__ __launch_bounds__(256) void gate_kernel(const float* __restrict__ x,
                                                   const float* __restrict__ Wg,
                                                   const float* __restrict__ bg) {
    int n = blockIdx.x;
    __shared__ float xs[DIM];
    __shared__ double score[NE];
    const float* xr = x + (size_t)n * DIM;
    for (int i = threadIdx.x; i < DIM; i += blockDim.x) xs[i] = xr[i];
    __syncthreads();

    int w = threadIdx.x >> 5, lane = threadIdx.x & 31;
    if (w < NE) {
        const float* wr = Wg + w * DIM;
        double acc = 0.0;
        for (int i = lane; i < DIM; i += 32) acc += (double)xs[i] * (double)wr[i];
#pragma unroll
        for (int o = 16; o; o >>= 1) acc += __shfl_xor_sync(0xffffffffu, acc, o);
        if (lane == 0) score[w] = acc + (double)bg[w];
    }
    __syncthreads();

    if (threadIdx.x == 0) {
        // smallest score; ties: larger index is excluded (jax keeps lower idx)
        int m1 = 0;
        for (int e = 1; e < NE; e++)
            if (score[e] < score[m1] || (score[e] == score[m1] && e > m1)) m1 = e;
        int m2 = -1;
        for (int e = 0; e < NE; e++) {
            if (e == m1) continue;
            if (m2 < 0 || score[e] < score[m2] || (score[e] == score[m2] && e > m2)) m2 = e;
        }
        int a = min(m1, m2), b = max(m1, m2);
        int pid = a * NE + b;
        int slot = atomicAdd(&g_cnt[pid], 1);
        g_list[pid * NTOK + slot] = n;
    }
}

// ============================================================
// Kernel 3: build (pattern, row-tile) work items
// ============================================================
__global__ void items_kernel() {
    if (threadIdx.x == 0 && blockIdx.x == 0) {
        int t = 0;
        for (int pid = 0; pid < NPAT; pid++) {
            int c = g_cnt[pid];
            for (int k = 0; k * TM < c && t < MAX_ITEMS; k++) {
                g_items[2 * t]     = pid;
                g_items[2 * t + 1] = k;
                t++;
            }
        }
        g_total = t;
    }
}

// ============================================================
// Kernel 4: gathered GEMM  out[tok] = x[tok] @ (Wsum-Wa-Wb)^T + bias
// 64x64 tile, TK=16, 256 threads, 4x4 accum per thread.
// ============================================================
__global__ __launch_bounds__(256) void gemm_kernel(const float* __restrict__ x,
                                                   const float* __restrict__ We,
                                                   const float* __restrict__ be,
                                                   float* __restrict__ out) {
    int item = blockIdx.x;
    if (item >= g_total) return;

    __shared__ float As[TK][TM];
    __shared__ float Bs[TK][TN];
    __shared__ int   toks[TM];

    int pid  = g_items[2 * item];
    int tile = g_items[2 * item + 1];
    int ea = pid >> 3, eb = pid & 7;
    int cnt  = g_cnt[pid];
    int row0 = tile * TM;
    int nrows = cnt - row0;
    if (nrows > TM) nrows = TM;
    const int* list = g_list + pid * NTOK + row0;

    int tid = threadIdx.x;
    if (tid < TM) toks[tid] = list[tid < nrows ? tid : 0];
    __syncthreads();

    int f0 = blockIdx.y * TN;
    const float* Wa = We + (size_t)ea * DIM * DIM;
    const float* Wb = We + (size_t)eb * DIM * DIM;

    int lr = tid >> 2;        // 0..63: row within tile for loads
    int ls = (tid & 3) * 4;   // 0,4,8,12: k-offset within k-tile
    int tx = tid & 15, ty = tid >> 4;

    const float* xrow  = x      + (size_t)toks[lr] * DIM + ls;
    const float* wsrow = g_Wsum + (size_t)(f0 + lr) * DIM + ls;
    const float* warow = Wa     + (size_t)(f0 + lr) * DIM + ls;
    const float* wbrow = Wb     + (size_t)(f0 + lr) * DIM + ls;

    float acc[4][4] = {};

    for (int k0 = 0; k0 < DIM; k0 += TK) {
        float4 av = *(const float4*)(xrow  + k0);
        float4 wv = *(const float4*)(wsrow + k0);
        float4 uv = *(const float4*)(warow + k0);
        float4 vv = *(const float4*)(wbrow + k0);
        wv.x -= uv.x + vv.x;
        wv.y -= uv.y + vv.y;
        wv.z -= uv.z + vv.z;
        wv.w -= uv.w + vv.w;
        __syncthreads();   // previous iter's reads done before overwrite
        As[ls + 0][lr] = av.x; As[ls + 1][lr] = av.y;
        As[ls + 2][lr] = av.z; As[ls + 3][lr] = av.w;
        Bs[ls + 0][lr] = wv.x; Bs[ls + 1][lr] = wv.y;
        Bs[ls + 2][lr] = wv.z; Bs[ls + 3][lr] = wv.w;
        __syncthreads();
#pragma unroll
        for (int k = 0; k < TK; k++) {
            float4 a4 = *(const float4*)&As[k][ty * 4];
            float4 b4 = *(const float4*)&Bs[k][tx * 4];
            acc[0][0] += a4.x * b4.x; acc[0][1] += a4.x * b4.y;
            acc[0][2] += a4.x * b4.z; acc[0][3] += a4.x * b4.w;
            acc[1][0] += a4.y * b4.x; acc[1][1] += a4.y * b4.y;
            acc[1][2] += a4.y * b4.z; acc[1][3] += a4.y * b4.w;
            acc[2][0] += a4.z * b4.x; acc[2][1] += a4.z * b4.y;
            acc[2][2] += a4.z * b4.z; acc[2][3] += a4.z * b4.w;
            acc[3][0] += a4.w * b4.x; acc[3][1] += a4.w * b4.y;
            acc[3][2] += a4.w * b4.z; acc[3][3] += a4.w * b4.w;
        }
    }

    int r = ty * 4, c = tx * 4;
#pragma unroll
    for (int i = 0; i < 4; i++) {
        int rr = r + i;
        if (rr < nrows) {
            int tok = toks[rr];
            float* o = out + (size_t)tok * DIM + f0 + c;
#pragma unroll
            for (int j = 0; j < 4; j++) {
                int f = f0 + c + j;
                o[j] = acc[i][j] + g_bsum[f] - be[ea * DIM + f] - be[eb * DIM + f];
            }
        }
    }
}

// ============================================================
extern "C" void kernel_launch(void* const* d_in, const int* in_sizes, int n_in,
                              void* d_out, int out_size) {
    const float* x  = (const float*)d_in[0];   // [8192, 2048]
    const float* Wg = (const float*)d_in[1];   // [8, 2048]
    const float* bg = (const float*)d_in[2];   // [8]
    const float* We = (const float*)d_in[3];   // [8, 2048, 2048]
    const float* be = (const float*)d_in[4];   // [8, 2048]
    float* out = (float*)d_out;                // [8192, 2048]

    prep_kernel<<<(DIM * DIM + 255) / 256, 256>>>(We, be);
    gate_kernel<<<NTOK, 256>>>(x, Wg, bg);
    items_kernel<<<1, 32>>>();
    dim3 grid(192, DIM / TN);   // 192 >= max work items
    gemm_kernel<<<grid, 256>>>(x, We, be, out);
}

// round 5
// speedup vs baseline: 3.0212x; 3.0212x over previous
#include <cuda_runtime.h>
#include <cuda_fp16.h>
#include <cstdint>

#define NTOK 8192
#define DIM  2048
#define NE   8
#define NPAIR 28
#define MAXI 96
#define TM   128
#define TN   128
#define TK   32
#define NSTG 4
#define KITERS (DIM / TK)   // 64

// ---------------- scratch (__device__ globals; no allocation) ----------------
__device__ __half g_Wp[(size_t)NPAIR * DIM * DIM];  // 28 fp16 pattern matrices (235 MB)
__device__ __half g_Xg[(size_t)NTOK * DIM];         // gathered fp16 X (32 MB)
__device__ int   g_cnt[64];
__device__ int   g_list[64 * NTOK];
__device__ int   g_perm[NTOK];
__device__ int   g_items[MAXI * 3];                 // (p28, m0, nrows)
__device__ int   g_total;

__device__ const int c_pa[NPAIR] = {0,0,0,0,0,0,0,1,1,1,1,1,1,2,2,2,2,2,3,3,3,3,4,4,4,5,5,6};
__device__ const int c_pb[NPAIR] = {1,2,3,4,5,6,7,2,3,4,5,6,7,3,4,5,6,7,4,5,6,7,5,6,7,6,7,7};

// ---------------- helpers ----------------
__device__ __forceinline__ uint32_t h2u(__half2 h) {
    return *reinterpret_cast<uint32_t*>(&h);
}
__device__ __forceinline__ uint32_t smem_u32(const void* p) {
    uint32_t a;
    asm("{ .reg .u64 t; cvta.to.shared.u64 t, %1; cvt.u32.u64 %0, t; }" : "=r"(a) : "l"(p));
    return a;
}
__device__ __forceinline__ void cp16(uint32_t s, const void* g) {
    asm volatile("cp.async.cg.shared.global [%0], [%1], 16;" :: "r"(s), "l"(g) : "memory");
}
__device__ __forceinline__ void cp_commit() {
    asm volatile("cp.async.commit_group;" ::: "memory");
}
__device__ __forceinline__ void cp_wait3() {
    asm volatile("cp.async.wait_group 3;" ::: "memory");
}
__device__ __forceinline__ void cp_wait_all() {
    asm volatile("cp.async.wait_all;" ::: "memory");
}
__device__ __forceinline__ void ldsm4(uint32_t* r, uint32_t a) {
    asm volatile("ldmatrix.sync.aligned.m8n8.x4.shared.b16 {%0,%1,%2,%3}, [%4];"
                 : "=r"(r[0]), "=r"(r[1]), "=r"(r[2]), "=r"(r[3]) : "r"(a));
}
__device__ __forceinline__ void mma16816(float* d, const uint32_t* a, uint32_t b0, uint32_t b1) {
    asm volatile("mma.sync.aligned.m16n8k16.row.col.f32.f16.f16.f32 "
        "{%0,%1,%2,%3}, {%4,%5,%6,%7}, {%8,%9}, {%0,%1,%2,%3};"
        : "+f"(d[0]), "+f"(d[1]), "+f"(d[2]), "+f"(d[3])
        : "r"(a[0]), "r"(a[1]), "r"(a[2]), "r"(a[3]), "r"(b0), "r"(b1));
}

// ---------------- kernel 0: zero counters ----------------
__global__ void zero_kernel() {
    if (threadIdx.x < 64) g_cnt[threadIdx.x] = 0;
    if (threadIdx.x == 0) g_total = 0;
}

// ---------------- kernel 1: gate (fp64 ranking, bucket by excluded pair) ----------------
__global__ __launch_bounds__(256) void gate_kernel(const float* __restrict__ x,
                                                   const float* __restrict__ Wg,
                                                   const float* __restrict__ bg) {
    int n = blockIdx.x;
    __shared__ float xs[DIM];
    __shared__ double score[NE];
    const float* xr = x + (size_t)n * DIM;
    for (int i = threadIdx.x; i < DIM; i += blockDim.x) xs[i] = xr[i];
    __syncthreads();

    int w = threadIdx.x >> 5, lane = threadIdx.x & 31;
    if (w < NE) {
        const float* wr = Wg + w * DIM;
        double acc = 0.0;
        for (int i = lane; i < DIM; i += 32) acc += (double)xs[i] * (double)wr[i];
#pragma unroll
        for (int o = 16; o; o >>= 1) acc += __shfl_xor_sync(0xffffffffu, acc, o);
        if (lane == 0) score[w] = acc + (double)bg[w];
    }
    __syncthreads();

    if (threadIdx.x == 0) {
        int m1 = 0;
        for (int e = 1; e < NE; e++)
            if (score[e] < score[m1] || (score[e] == score[m1] && e > m1)) m1 = e;
        int m2 = -1;
        for (int e = 0; e < NE; e++) {
            if (e == m1) continue;
            if (m2 < 0 || score[e] < score[m2] || (score[e] == score[m2] && e > m2)) m2 = e;
        }
        int a = min(m1, m2), b = max(m1, m2);
        int pid = a * NE + b;
        int slot = atomicAdd(&g_cnt[pid], 1);
        g_list[pid * NTOK + slot] = n;
    }
}

// ---------------- kernel 2: scan -> items + perm ----------------
__global__ void scan_kernel() {
    __shared__ int off[NPAIR];
    if (threadIdx.x == 0) {
        int rowoff = 0, t = 0;
        for (int p = 0; p < NPAIR; p++) {
            int pid = c_pa[p] * 8 + c_pb[p];
            int c = g_cnt[pid];
            off[p] = rowoff;
            for (int r = 0; r < c && t < MAXI; r += TM) {
                g_items[3 * t] = p;
                g_items[3 * t + 1] = rowoff + r;
                g_items[3 * t + 2] = min(TM, c - r);
                t++;
            }
            rowoff += c;
        }
        g_total = t;
    }
    __syncthreads();
    int p = threadIdx.x;
    if (p < NPAIR) {
        int pid = c_pa[p] * 8 + c_pb[p];
        int c = g_cnt[pid], o = off[p];
        for (int i = 0; i < c; i++) g_perm[o + i] = g_list[pid * NTOK + i];
    }
}

// ---------------- kernel 3: gather X -> fp16 Xg ----------------
__global__ __launch_bounds__(256) void gather_kernel(const float* __restrict__ x) {
    int j = blockIdx.x;
    int tok = g_perm[j];
    const float4* src = (const float4*)(x + (size_t)tok * DIM);
    uint4* dst = (uint4*)(g_Xg + (size_t)j * DIM);
    for (int i = threadIdx.x; i < DIM / 8; i += 256) {
        float4 v0 = src[2 * i], v1 = src[2 * i + 1];
        uint4 o;
        o.x = h2u(__floats2half2_rn(v0.x, v0.y));
        o.y = h2u(__floats2half2_rn(v0.z, v0.w));
        o.z = h2u(__floats2half2_rn(v1.x, v1.y));
        o.w = h2u(__floats2half2_rn(v1.z, v1.w));
        dst[i] = o;
    }
}

// ---------------- kernel 4: build 28 fp16 pattern matrices ----------------
__global__ __launch_bounds__(256) void build_kernel(const float* __restrict__ We) {
    size_t i4 = (size_t)blockIdx.x * 256 + threadIdx.x;   // float4 index into DIM*DIM
    float4 v[NE];
    float4 s = make_float4(0.f, 0.f, 0.f, 0.f);
#pragma unroll
    for (int e = 0; e < NE; e++) {
        v[e] = ((const float4*)(We + (size_t)e * DIM * DIM))[i4];
        s.x += v[e].x; s.y += v[e].y; s.z += v[e].z; s.w += v[e].w;
    }
#pragma unroll
    for (int p = 0; p < NPAIR; p++) {
        int a = c_pa[p], b = c_pb[p];
        uint2 o;
        o.x = h2u(__floats2half2_rn(s.x - v[a].x - v[b].x, s.y - v[a].y - v[b].y));
        o.y = h2u(__floats2half2_rn(s.z - v[a].z - v[b].z, s.w - v[a].w - v[b].w));
        ((uint2*)(g_Wp + (size_t)p * DIM * DIM))[i4] = o;
    }
}

// ---------------- kernel 5: mma.sync fp16 GEMM ----------------
// dyn smem: stages [0, NSTG*16KB): stage s = A(8KB) then B(8KB); bias @65536; toks @66048
#define STG_BYTES 16384
#define OFF_BIAS  (NSTG * STG_BYTES)
#define OFF_TOKS  (OFF_BIAS + 512)
#define SMEM_TOTAL (OFF_TOKS + 512)

__device__ __forceinline__ uint32_t swz(int row, int kc) {   // chunk swizzle, conflict-free ldmatrix
    return (uint32_t)(row * 64 + ((kc ^ ((row >> 1) & 3)) << 4));
}

__global__ __launch_bounds__(256) void gemm_kernel(const float* __restrict__ be,
                                                   float* __restrict__ out) {
    int item = blockIdx.x;
    if (item >= g_total) return;
    extern __shared__ char smem[];
    uint32_t sb = smem_u32(smem);
    int tid = threadIdx.x, wid = tid >> 5, lane = tid & 31;

    int p     = g_items[3 * item];
    int m0    = g_items[3 * item + 1];
    int nrows = g_items[3 * item + 2];
    int ea = c_pa[p], eb = c_pb[p];
    int n0 = blockIdx.y * TN;

    // bias + token list into smem (outside the pipeline region)
    float* sbias = (float*)(smem + OFF_BIAS);
    int*   stoks = (int*)(smem + OFF_TOKS);
    if (tid < TN) {
        float bs = 0.f;
#pragma unroll
        for (int e = 0; e < NE; e++)
            if (e != ea && e != eb) bs += be[e * DIM + n0 + tid];
        sbias[tid] = bs;
        stoks[tid] = (tid < nrows) ? g_perm[m0 + tid] : -1;
    }

    // cp.async thread mapping: 2 passes of 64 rows; 4 chunks of 16B per row
    int crow = tid >> 2;        // 0..63
    int cchk = tid & 3;         // 0..3
    const __half* Abase = g_Xg + (size_t)min(m0 + crow, NTOK - 1) * DIM + cchk * 8;
    const __half* A2    = g_Xg + (size_t)min(m0 + 64 + crow, NTOK - 1) * DIM + cchk * 8;
    const __half* Bbase = g_Wp + ((size_t)p * DIM + (n0 + crow)) * DIM + cchk * 8;
    const __half* B2    = Bbase + (size_t)64 * DIM;
    uint32_t dA1 = swz(crow, cchk), dA2 = swz(64 + crow, cchk);

    float acc[4][4][4];
#pragma unroll
    for (int i = 0; i < 4; i++)
#pragma unroll
        for (int j = 0; j < 4; j++)
#pragma unroll
            for (int k = 0; k < 4; k++) acc[i][j][k] = 0.f;

    // prologue: issue stages 0..NSTG-2
#pragma unroll
    for (int s = 0; s < NSTG - 1; s++) {
        uint32_t st = sb + s * STG_BYTES;
        int ko = s * TK;
        cp16(st + dA1, Abase + ko);
        cp16(st + dA2, A2 + ko);
        cp16(st + 8192 + dA1, Bbase + ko);
        cp16(st + 8192 + dA2, B2 + ko);
        cp_commit();
    }

    int m0w = (wid & 1) * 64, n0w = (wid >> 1) * 32;
    // precomputed ldmatrix smem offsets (stage-relative)
    uint32_t aoff[2][4], boff[2][2];
#pragma unroll
    for (int kg = 0; kg < 2; kg++) {
#pragma unroll
        for (int mf = 0; mf < 4; mf++) {
            int row = m0w + mf * 16 + (lane & 7) + ((lane >> 3) & 1) * 8;
            int kc = kg * 2 + ((lane >> 4) & 1);
            aoff[kg][mf] = swz(row, kc);
        }
#pragma unroll
        for (int np = 0; np < 2; np++) {
            int nn = n0w + np * 16 + (lane & 7) + ((lane >> 4) & 1) * 8;
            int kc = kg * 2 + ((lane >> 3) & 1);
            boff[kg][np] = 8192u + swz(nn, kc);
        }
    }

    for (int kt = 0; kt < KITERS; kt++) {
        // issue stage kt+NSTG-1
        if (kt + NSTG - 1 < KITERS) {
            uint32_t st = sb + ((kt + NSTG - 1) % NSTG) * STG_BYTES;
            int ko = (kt + NSTG - 1) * TK;
            cp16(st + dA1, Abase + ko);
            cp16(st + dA2, A2 + ko);
            cp16(st + 8192 + dA1, Bbase + ko);
            cp16(st + 8192 + dA2, B2 + ko);
            cp_commit();
            cp_wait3();
        } else {
            cp_wait_all();
        }
        __syncthreads();

        uint32_t st = sb + (kt % NSTG) * STG_BYTES;
#pragma unroll
        for (int kg = 0; kg < 2; kg++) {
            uint32_t afr[4][4];
#pragma unroll
            for (int mf = 0; mf < 4; mf++) ldsm4(afr[mf], st + aoff[kg][mf]);
            uint32_t bfr[2][4];
#pragma unroll
            for (int np = 0; np < 2; np++) ldsm4(bfr[np], st + boff[kg][np]);
#pragma unroll
            for (int mf = 0; mf < 4; mf++)
#pragma unroll
                for (int nf = 0; nf < 4; nf++)
                    mma16816(acc[mf][nf], afr[mf], bfr[nf >> 1][(nf & 1) * 2],
                             bfr[nf >> 1][(nf & 1) * 2 + 1]);
        }
        __syncthreads();
    }

    // epilogue: bias + scatter (stoks/sbias already resident)
#pragma unroll
    for (int mf = 0; mf < 4; mf++) {
        int rbase = m0w + mf * 16 + (lane >> 2);
        int t0 = stoks[rbase], t1 = stoks[rbase + 8];
#pragma unroll
        for (int nf = 0; nf < 4; nf++) {
            int cbase = n0w + nf * 8 + (lane & 3) * 2;
            float b0 = sbias[cbase], b1 = sbias[cbase + 1];
            if (t0 >= 0) {
                float2 o = make_float2(acc[mf][nf][0] + b0, acc[mf][nf][1] + b1);
                *(float2*)(out + (size_t)t0 * DIM + n0 + cbase) = o;
            }
            if (t1 >= 0) {
                float2 o = make_float2(acc[mf][nf][2] + b0, acc[mf][nf][3] + b1);
                *(float2*)(out + (size_t)t1 * DIM + n0 + cbase) = o;
            }
        }
    }
}

// ---------------- host ----------------
extern "C" void kernel_launch(void* const* d_in, const int* in_sizes, int n_in,
                              void* d_out, int out_size) {
    const float* x  = (const float*)d_in[0];
    const float* Wg = (const float*)d_in[1];
    const float* bg = (const float*)d_in[2];
    const float* We = (const float*)d_in[3];
    const float* be = (const float*)d_in[4];
    float* out = (float*)d_out;

    static bool attr_set = false;
    if (!attr_set) {
        cudaFuncSetAttribute(gemm_kernel, cudaFuncAttributeMaxDynamicSharedMemorySize, SMEM_TOTAL);
        attr_set = true;
    }

    zero_kernel<<<1, 64>>>();
    gate_kernel<<<NTOK, 256>>>(x, Wg, bg);
    scan_kernel<<<1, 32>>>();
    gather_kernel<<<NTOK, 256>>>(x);
    build_kernel<<<DIM * DIM / (256 * 4), 256>>>(We);
    dim3 grid(MAXI, DIM / TN);
    gemm_kernel<<<grid, 256, SMEM_TOTAL>>>(be, out);
}

// round 6
// speedup vs baseline: 3.1242x; 1.0341x over previous
#include <cuda_runtime.h>
#include <cuda_fp16.h>
#include <cstdint>

#define NTOK 8192
#define DIM  2048
#define NE   8
#define NPAIR 28
#define MAXI 96
#define TM   128
#define TN   128
#define TK   32
#define NSTG 6
#define KITERS (DIM / TK)   // 64

// ---------------- scratch (__device__ globals; no allocation) ----------------
__device__ __half g_Wp[(size_t)NPAIR * DIM * DIM];  // 28 fp16 pattern matrices (235 MB)
__device__ __half g_Xg[(size_t)NTOK * DIM];         // gathered fp16 X (32 MB)
__device__ int   g_cnt[64];
__device__ int   g_list[64 * NTOK];
__device__ int   g_perm[NTOK];
__device__ int   g_items[MAXI * 3];                 // (p28, m0, nrows)
__device__ int   g_total;

__device__ const int c_pa[NPAIR] = {0,0,0,0,0,0,0,1,1,1,1,1,1,2,2,2,2,2,3,3,3,3,4,4,4,5,5,6};
__device__ const int c_pb[NPAIR] = {1,2,3,4,5,6,7,2,3,4,5,6,7,3,4,5,6,7,4,5,6,7,5,6,7,6,7,7};

// ---------------- helpers ----------------
__device__ __forceinline__ uint32_t h2u(__half2 h) {
    return *reinterpret_cast<uint32_t*>(&h);
}
__device__ __forceinline__ uint32_t smem_u32(const void* p) {
    uint32_t a;
    asm("{ .reg .u64 t; cvta.to.shared.u64 t, %1; cvt.u32.u64 %0, t; }" : "=r"(a) : "l"(p));
    return a;
}
__device__ __forceinline__ void cp16(uint32_t s, const void* g) {
    asm volatile("cp.async.cg.shared.global [%0], [%1], 16;" :: "r"(s), "l"(g) : "memory");
}
__device__ __forceinline__ void cp_commit() {
    asm volatile("cp.async.commit_group;" ::: "memory");
}
template <int N>
__device__ __forceinline__ void cp_wait() {
    asm volatile("cp.async.wait_group %0;" :: "n"(N) : "memory");
}
__device__ __forceinline__ void cp_wait_all() {
    asm volatile("cp.async.wait_all;" ::: "memory");
}
__device__ __forceinline__ void ldsm4(uint32_t* r, uint32_t a) {
    asm volatile("ldmatrix.sync.aligned.m8n8.x4.shared.b16 {%0,%1,%2,%3}, [%4];"
                 : "=r"(r[0]), "=r"(r[1]), "=r"(r[2]), "=r"(r[3]) : "r"(a));
}
__device__ __forceinline__ void mma16816(float* d, const uint32_t* a, uint32_t b0, uint32_t b1) {
    asm volatile("mma.sync.aligned.m16n8k16.row.col.f32.f16.f16.f32 "
        "{%0,%1,%2,%3}, {%4,%5,%6,%7}, {%8,%9}, {%0,%1,%2,%3};"
        : "+f"(d[0]), "+f"(d[1]), "+f"(d[2]), "+f"(d[3])
        : "r"(a[0]), "r"(a[1]), "r"(a[2]), "r"(a[3]), "r"(b0), "r"(b1));
}

// ---------------- kernel 0: zero counters ----------------
__global__ void zero_kernel() {
    if (threadIdx.x < 64) g_cnt[threadIdx.x] = 0;
    if (threadIdx.x == 0) g_total = 0;
}

// ---------------- kernel 1: gate (fp64 ranking, bucket by excluded pair) ----------------
__global__ __launch_bounds__(256) void gate_kernel(const float* __restrict__ x,
                                                   const float* __restrict__ Wg,
                                                   const float* __restrict__ bg) {
    int n = blockIdx.x;
    __shared__ float xs[DIM];
    __shared__ double score[NE];
    const float* xr = x + (size_t)n * DIM;
    for (int i = threadIdx.x; i < DIM; i += blockDim.x) xs[i] = xr[i];
    __syncthreads();

    int w = threadIdx.x >> 5, lane = threadIdx.x & 31;
    if (w < NE) {
        const float* wr = Wg + w * DIM;
        double acc = 0.0;
        for (int i = lane; i < DIM; i += 32) acc += (double)xs[i] * (double)wr[i];
#pragma unroll
        for (int o = 16; o; o >>= 1) acc += __shfl_xor_sync(0xffffffffu, acc, o);
        if (lane == 0) score[w] = acc + (double)bg[w];
    }
    __syncthreads();

    if (threadIdx.x == 0) {
        int m1 = 0;
        for (int e = 1; e < NE; e++)
            if (score[e] < score[m1] || (score[e] == score[m1] && e > m1)) m1 = e;
        int m2 = -1;
        for (int e = 0; e < NE; e++) {
            if (e == m1) continue;
            if (m2 < 0 || score[e] < score[m2] || (score[e] == score[m2] && e > m2)) m2 = e;
        }
        int a = min(m1, m2), b = max(m1, m2);
        int pid = a * NE + b;
        int slot = atomicAdd(&g_cnt[pid], 1);
        g_list[pid * NTOK + slot] = n;
    }
}

// ---------------- kernel 2: scan -> items + perm ----------------
__global__ void scan_kernel() {
    __shared__ int off[NPAIR];
    if (threadIdx.x == 0) {
        int rowoff = 0, t = 0;
        for (int p = 0; p < NPAIR; p++) {
            int pid = c_pa[p] * 8 + c_pb[p];
            int c = g_cnt[pid];
            off[p] = rowoff;
            for (int r = 0; r < c && t < MAXI; r += TM) {
                g_items[3 * t] = p;
                g_items[3 * t + 1] = rowoff + r;
                g_items[3 * t + 2] = min(TM, c - r);
                t++;
            }
            rowoff += c;
        }
        g_total = t;
    }
    __syncthreads();
    int p = threadIdx.x;
    if (p < NPAIR) {
        int pid = c_pa[p] * 8 + c_pb[p];
        int c = g_cnt[pid], o = off[p];
        for (int i = 0; i < c; i++) g_perm[o + i] = g_list[pid * NTOK + i];
    }
}

// ---------------- kernel 3: gather X -> fp16 Xg ----------------
__global__ __launch_bounds__(256) void gather_kernel(const float* __restrict__ x) {
    int j = blockIdx.x;
    int tok = g_perm[j];
    const float4* src = (const float4*)(x + (size_t)tok * DIM);
    uint4* dst = (uint4*)(g_Xg + (size_t)j * DIM);
    for (int i = threadIdx.x; i < DIM / 8; i += 256) {
        float4 v0 = src[2 * i], v1 = src[2 * i + 1];
        uint4 o;
        o.x = h2u(__floats2half2_rn(v0.x, v0.y));
        o.y = h2u(__floats2half2_rn(v0.z, v0.w));
        o.z = h2u(__floats2half2_rn(v1.x, v1.y));
        o.w = h2u(__floats2half2_rn(v1.z, v1.w));
        dst[i] = o;
    }
}

// ---------------- kernel 4: build 28 fp16 pattern matrices ----------------
__global__ __launch_bounds__(256) void build_kernel(const float* __restrict__ We) {
    size_t i4 = (size_t)blockIdx.x * 256 + threadIdx.x;   // float4 index into DIM*DIM
    float4 v[NE];
    float4 s = make_float4(0.f, 0.f, 0.f, 0.f);
#pragma unroll
    for (int e = 0; e < NE; e++) {
        v[e] = ((const float4*)(We + (size_t)e * DIM * DIM))[i4];
        s.x += v[e].x; s.y += v[e].y; s.z += v[e].z; s.w += v[e].w;
    }
#pragma unroll
    for (int p = 0; p < NPAIR; p++) {
        int a = c_pa[p], b = c_pb[p];
        uint2 o;
        o.x = h2u(__floats2half2_rn(s.x - v[a].x - v[b].x, s.y - v[a].y - v[b].y));
        o.y = h2u(__floats2half2_rn(s.z - v[a].z - v[b].z, s.w - v[a].w - v[b].w));
        ((uint2*)(g_Wp + (size_t)p * DIM * DIM))[i4] = o;
    }
}

// ---------------- kernel 5: mma.sync fp16 GEMM ----------------
// 4 warps, warp tile 64x64, CTA tile 128x128, TK=32, NSTG=6, one sync per k-iter.
// dyn smem: stage s @ s*16KB: A(8KB) then B(8KB); bias @NSTG*16KB; toks after.
#define STG_BYTES 16384
#define OFF_BIAS  (NSTG * STG_BYTES)
#define OFF_TOKS  (OFF_BIAS + 512)
#define SMEM_TOTAL (OFF_TOKS + 512)

__device__ __forceinline__ uint32_t swz(int row, int kc) {   // chunk swizzle, conflict-free ldmatrix
    return (uint32_t)(row * 64 + ((kc ^ ((row >> 1) & 3)) << 4));
}

__global__ __launch_bounds__(128, 2) void gemm_kernel(const float* __restrict__ be,
                                                      float* __restrict__ out) {
    int item = blockIdx.x;
    if (item >= g_total) return;
    extern __shared__ char smem[];
    uint32_t sb = smem_u32(smem);
    int tid = threadIdx.x, wid = tid >> 5, lane = tid & 31;

    int p     = g_items[3 * item];
    int m0    = g_items[3 * item + 1];
    int nrows = g_items[3 * item + 2];
    int ea = c_pa[p], eb = c_pb[p];
    int n0 = blockIdx.y * TN;

    // bias + token list into smem (outside the pipeline region)
    float* sbias = (float*)(smem + OFF_BIAS);
    int*   stoks = (int*)(smem + OFF_TOKS);
    {
        float bs = 0.f;
#pragma unroll
        for (int e = 0; e < NE; e++)
            if (e != ea && e != eb) bs += be[e * DIM + n0 + tid];
        sbias[tid] = bs;
        stoks[tid] = (tid < nrows) ? g_perm[m0 + tid] : -1;
    }

    // cp.async mapping: 4 passes of 32 rows; 4 chunks of 16B per row
    int crow = tid >> 2;        // 0..31
    int cchk = tid & 3;         // 0..3
    const __half* srcA[4];
    const __half* srcB[4];
    uint32_t dA[4];
#pragma unroll
    for (int ps = 0; ps < 4; ps++) {
        int ra = min(m0 + crow + 32 * ps, NTOK - 1);
        srcA[ps] = g_Xg + (size_t)ra * DIM + cchk * 8;
        srcB[ps] = g_Wp + ((size_t)p * DIM + (n0 + crow + 32 * ps)) * DIM + cchk * 8;
        dA[ps] = swz(crow + 32 * ps, cchk);
    }

    float acc[4][8][4];
#pragma unroll
    for (int i = 0; i < 4; i++)
#pragma unroll
        for (int j = 0; j < 8; j++)
#pragma unroll
            for (int k = 0; k < 4; k++) acc[i][j][k] = 0.f;

    // prologue: issue stages 0..NSTG-2
#pragma unroll
    for (int s = 0; s < NSTG - 1; s++) {
        uint32_t st = sb + s * STG_BYTES;
        int ko = s * TK;
#pragma unroll
        for (int ps = 0; ps < 4; ps++) {
            cp16(st + dA[ps], srcA[ps] + ko);
            cp16(st + 8192 + dA[ps], srcB[ps] + ko);
        }
        cp_commit();
    }

    int m0w = (wid & 1) * 64, n0w = (wid >> 1) * 64;
    // precomputed ldmatrix smem offsets (stage-relative)
    uint32_t aoff[2][4], boff[2][4];
#pragma unroll
    for (int kg = 0; kg < 2; kg++) {
#pragma unroll
        for (int mf = 0; mf < 4; mf++) {
            int row = m0w + mf * 16 + (lane & 7) + ((lane >> 3) & 1) * 8;
            int kc = kg * 2 + ((lane >> 4) & 1);
            aoff[kg][mf] = swz(row, kc);
        }
#pragma unroll
        for (int np = 0; np < 4; np++) {
            int nn = n0w + np * 16 + (lane & 7) + ((lane >> 4) & 1) * 8;
            int kc = kg * 2 + ((lane >> 3) & 1);
            boff[kg][np] = 8192u + swz(nn, kc);
        }
    }

#define COMPUTE_KT(kt_)                                                          \
    do {                                                                         \
        uint32_t st = sb + ((kt_) % NSTG) * STG_BYTES;                           \
        _Pragma("unroll")                                                        \
        for (int kg = 0; kg < 2; kg++) {                                         \
            uint32_t afr[4][4];                                                  \
            _Pragma("unroll")                                                    \
            for (int mf = 0; mf < 4; mf++) ldsm4(afr[mf], st + aoff[kg][mf]);    \
            uint32_t bfr[4][4];                                                  \
            _Pragma("unroll")                                                    \
            for (int np = 0; np < 4; np++) ldsm4(bfr[np], st + boff[kg][np]);    \
            _Pragma("unroll")                                                    \
            for (int mf = 0; mf < 4; mf++)                                       \
                _Pragma("unroll")                                                \
                for (int nf = 0; nf < 8; nf++)                                   \
                    mma16816(acc[mf][nf], afr[mf], bfr[nf >> 1][(nf & 1) * 2],   \
                             bfr[nf >> 1][(nf & 1) * 2 + 1]);                    \
        }                                                                        \
    } while (0)

    // main loop: one __syncthreads per k-iter
    for (int kt = 0; kt < KITERS - (NSTG - 1); kt++) {
        cp_wait<NSTG - 2>();        // this thread's stage-kt copies done
        __syncthreads();            // visibility + WAR for stage about to be rewritten
        {
            uint32_t st = sb + ((kt + NSTG - 1) % NSTG) * STG_BYTES;
            int ko = (kt + NSTG - 1) * TK;
#pragma unroll
            for (int ps = 0; ps < 4; ps++) {
                cp16(st + dA[ps], srcA[ps] + ko);
                cp16(st + 8192 + dA[ps], srcB[ps] + ko);
            }
            cp_commit();
        }
        COMPUTE_KT(kt);
    }
    // tail: all data already issued; drain once, then sync-free compute
    cp_wait_all();
    __syncthreads();
#pragma unroll
    for (int j = 0; j < NSTG - 1; j++) {
        int kt = KITERS - (NSTG - 1) + j;
        COMPUTE_KT(kt);
    }

    // epilogue: bias + scatter (stoks/sbias resident)
#pragma unroll
    for (int mf = 0; mf < 4; mf++) {
        int rbase = m0w + mf * 16 + (lane >> 2);
        int t0 = stoks[rbase], t1 = stoks[rbase + 8];
#pragma unroll
        for (int nf = 0; nf < 8; nf++) {
            int cbase = n0w + nf * 8 + (lane & 3) * 2;
            float b0 = sbias[cbase], b1 = sbias[cbase + 1];
            if (t0 >= 0) {
                float2 o = make_float2(acc[mf][nf][0] + b0, acc[mf][nf][1] + b1);
                *(float2*)(out + (size_t)t0 * DIM + n0 + cbase) = o;
            }
            if (t1 >= 0) {
                float2 o = make_float2(acc[mf][nf][2] + b0, acc[mf][nf][3] + b1);
                *(float2*)(out + (size_t)t1 * DIM + n0 + cbase) = o;
            }
        }
    }
}

// ---------------- host ----------------
extern "C" void kernel_launch(void* const* d_in, const int* in_sizes, int n_in,
                              void* d_out, int out_size) {
    const float* x  = (const float*)d_in[0];
    const float* Wg = (const float*)d_in[1];
    const float* bg = (const float*)d_in[2];
    const float* We = (const float*)d_in[3];
    const float* be = (const float*)d_in[4];
    float* out = (float*)d_out;

    static bool attr_set = false;
    if (!attr_set) {
        cudaFuncSetAttribute(gemm_kernel, cudaFuncAttributeMaxDynamicSharedMemorySize, SMEM_TOTAL);
        attr_set = true;
    }

    zero_kernel<<<1, 64>>>();
    gate_kernel<<<NTOK, 256>>>(x, Wg, bg);
    scan_kernel<<<1, 32>>>();
    gather_kernel<<<NTOK, 256>>>(x);
    build_kernel<<<DIM * DIM / (256 * 4), 256>>>(We);
    dim3 grid(MAXI, DIM / TN);
    gemm_kernel<<<grid, 128, SMEM_TOTAL>>>(be, out);
}